// round 11
// baseline (speedup 1.0000x reference)
#include <cuda_runtime.h>
#include <cuda_fp16.h>
#include <cstdint>
#include <cmath>

// ---------------- problem constants ----------------
#define NTOK 8192      // B*T
#define DDIM 2048
#define NE   64

// output layout (concatenated float32)
#define P_OFF 0
#define I_OFF (NTOK * NE)
#define M_OFF (I_OFF + NTOK * 2)

// ---------------- GEMM tiling ----------------
#define KSPLIT 2
#define KQ     1024           // K per split
#define CHK    32             // k per chunk
#define NCH    32             // chunks (KQ/CHK)
#define AROW   80             // smem row stride bytes (64B data + 16B pad)
#define A_PL   (128 * AROW)   // A plane: 128 tokens (10240)
#define B_PL   (128 * AROW)   // B plane: 128 cols   (10240)
#define A_SZ   (2 * A_PL)     // 20480
#define B_SZ   (2 * B_PL)     // 20480
#define BUF    (A_SZ + B_SZ)  // 40960
#define SMEMB  (2 * BUF)      // 81920, double buffered

// ---------------- scratch ----------------
__device__ __align__(16) __half g_B[2 * 128 * 2048];   // [plane][col][k] fp16
__device__ float g_part[KSPLIT * NTOK * 128];          // k-split partials (8MB)
__device__ int   g_ctr[64];                            // per-tile counters (self-reset)

// ---------------- helpers ----------------
__device__ __forceinline__ uint32_t smem_u32(const void* p) {
    uint32_t a;
    asm("{ .reg .u64 t; cvta.to.shared.u64 t, %1; cvt.u32.u64 %0, t; }" : "=r"(a) : "l"(p));
    return a;
}
#define CP16(dst, src) \
    asm volatile("cp.async.cg.shared.global [%0], [%1], 16;" :: "r"(dst), "l"(src) : "memory")
#define CP_COMMIT() asm volatile("cp.async.commit_group;" ::: "memory")
#define CP_WAIT0()  asm volatile("cp.async.wait_group 0;" ::: "memory")

__device__ __forceinline__ void ldsm4(uint32_t (&r)[4], uint32_t addr) {
    asm volatile("ldmatrix.sync.aligned.m8n8.x4.shared.b16 {%0,%1,%2,%3}, [%4];"
                 : "=r"(r[0]), "=r"(r[1]), "=r"(r[2]), "=r"(r[3]) : "r"(addr));
}
__device__ __forceinline__ void mma16816(float (&c)[4], const uint32_t (&a)[4],
                                         uint32_t b0, uint32_t b1) {
    asm volatile(
        "mma.sync.aligned.m16n8k16.row.col.f32.f16.f16.f32 "
        "{%0,%1,%2,%3},{%4,%5,%6,%7},{%8,%9},{%0,%1,%2,%3};"
        : "+f"(c[0]), "+f"(c[1]), "+f"(c[2]), "+f"(c[3])
        : "r"(a[0]), "r"(a[1]), "r"(a[2]), "r"(a[3]), "r"(b0), "r"(b1));
}
__device__ __forceinline__ uint32_t h2_bits(__half2 v) {
    return *reinterpret_cast<uint32_t*>(&v);
}
// split 8 fp32 -> 2 planes of 8 fp16 (packed uint4 each)
__device__ __forceinline__ void split8h(const float* f, uint4& H, uint4& L) {
    uint32_t hw[4], lw[4];
    #pragma unroll
    for (int i = 0; i < 4; i++) {
        float a = f[2 * i], b = f[2 * i + 1];
        __half2 hp = __floats2half2_rn(a, b);
        float ra = a - __low2float(hp);
        float rb = b - __high2float(hp);
        __half2 lp = __floats2half2_rn(ra, rb);
        hw[i] = h2_bits(hp); lw[i] = h2_bits(lp);
    }
    H = make_uint4(hw[0], hw[1], hw[2], hw[3]);
    L = make_uint4(lw[0], lw[1], lw[2], lw[3]);
}
__device__ __forceinline__ float softplus_f(float v) {
    return (v > 20.0f) ? v : log1pf(expf(v));
}
__device__ __forceinline__ void top2_merge(float& v1, int& i1, float& v2, int& i2,
                                           float ov1, int oi1, float ov2, int oi2) {
    bool ow = (ov1 > v1) || (ov1 == v1 && oi1 < i1);
    float nv1 = ow ? ov1 : v1;  int ni1 = ow ? oi1 : i1;
    float lv  = ow ? v1  : ov1; int li  = ow ? i1  : oi1;
    float wv2 = ow ? ov2 : v2;  int wi2 = ow ? oi2 : i2;
    bool sw = (lv > wv2) || (lv == wv2 && li < wi2);
    v1 = nv1; i1 = ni1;
    v2 = sw ? lv : wv2; i2 = sw ? li : wi2;
}

// fragment-group loaders (volatile asm keeps source order = manual schedule)
__device__ __forceinline__ void ldsm_A(uint32_t (&F)[2][4], uint32_t aB, int m0,
                                       uint32_t a_lane, int s, int poff) {
    #pragma unroll
    for (int mf = 0; mf < 2; mf++)
        ldsm4(F[mf], aB + (uint32_t)((m0 + mf * 16) * AROW) + a_lane + s * 32 + poff);
}
__device__ __forceinline__ void ldsm_B(uint32_t (&F)[2][4], uint32_t bB, int n0w,
                                       uint32_t b_lane, int s, int poff) {
    #pragma unroll
    for (int q = 0; q < 2; q++)
        ldsm4(F[q], bB + (uint32_t)((n0w + q * 16) * AROW) + b_lane + s * 32 + poff);
}
__device__ __forceinline__ void pass(float (&acc)[2][4][4], const uint32_t (&A)[2][4],
                                     const uint32_t (&B)[2][4]) {
    #pragma unroll
    for (int mf = 0; mf < 2; mf++)
        #pragma unroll
        for (int nf = 0; nf < 4; nf++)
            mma16816(acc[mf][nf], A[mf], B[nf >> 1][(nf & 1) * 2], B[nf >> 1][(nf & 1) * 2 + 1]);
}

// ---------------- prep: w -> g_B[2][128 col][2048 k] fp16, smem transpose ----------------
__global__ __launch_bounds__(256) void prep_b(const float* __restrict__ wg,
                                              const float* __restrict__ wn) {
    __shared__ __align__(16) __half sh[2][64][36];  // [plane][n][32k + pad]
    const int tid = threadIdx.x;
    const int h  = blockIdx.x & 1;
    const int k0 = (blockIdx.x >> 1) * 32;
    const float* w = h ? wn : wg;

    #pragma unroll
    for (int i = 0; i < 8; i++) {
        int fid = i * 256 + tid;
        int kk = fid >> 6;
        int n  = fid & 63;
        float a = w[(k0 + kk) * 64 + n];
        __half hh = __float2half_rn(a);
        __half hl = __float2half_rn(a - __half2float(hh));
        sh[0][n][kk] = hh;
        sh[1][n][kk] = hl;
    }
    __syncthreads();

    #pragma unroll
    for (int i = 0; i < 4; i++) {
        int fid = i * 256 + tid;
        int plane = fid >> 9;
        int rem = fid & 511;
        int row = rem >> 3;
        int kq  = rem & 7;
        uint2 v = *reinterpret_cast<const uint2*>(&sh[plane][row][kq * 4]);
        *reinterpret_cast<uint2*>(&g_B[(plane * 128 + h * 64 + row) * 2048 + k0 + kq * 4]) = v;
    }
}

// ---------------- fused GEMM + router ----------------
__global__ __launch_bounds__(512, 1) void gemm_fused(
    const float* __restrict__ x, const float* __restrict__ eps,
    float* __restrict__ out)
{
    extern __shared__ char smem[];
    __shared__ int s_flag;
    const uint32_t sb = smem_u32(smem);
    const int tid  = threadIdx.x;
    const int wid  = tid >> 5;
    const int lane = tid & 31;
    const int tile = blockIdx.x >> 1;
    const int ks   = blockIdx.x & 1;
    const long t0  = (long)tile * 128;
    const int kbase = ks * KQ;

    const int m0  = (wid & 3) * 32;
    const int n0w = (wid >> 2) * 32;

    const int am = tid >> 2;
    const int aq = tid & 3;

    float acc[2][4][4];
    #pragma unroll
    for (int a = 0; a < 2; a++)
        #pragma unroll
        for (int b = 0; b < 4; b++)
            #pragma unroll
            for (int c = 0; c < 4; c++) acc[a][b][c] = 0.0f;

    const int t4 = lane >> 3, r8 = lane & 7;
    const uint32_t a_lane = (uint32_t)(((t4 & 1) * 8 + r8) * AROW + (t4 >> 1) * 16);
    const uint32_t b_lane = (uint32_t)(((t4 >> 1) * 8 + r8) * AROW + (t4 & 1) * 16);

    float4 sxa, sxb;   // staged A chunk

    #define LOAD_A(ch) do {                                                            \
        const float4* px = reinterpret_cast<const float4*>(                            \
            x + (t0 + am) * DDIM + kbase + (ch) * CHK + aq * 8);                       \
        sxa = px[0]; sxb = px[1];                                                      \
    } while (0)

    #define STORE_A(buf) do {                                                          \
        uint4 H, L;                                                                    \
        float f[8] = {sxa.x, sxa.y, sxa.z, sxa.w, sxb.x, sxb.y, sxb.z, sxb.w};         \
        split8h(f, H, L);                                                              \
        *reinterpret_cast<uint4*>(smem + (buf) + 0 * A_PL + am * AROW + aq * 16) = H;  \
        *reinterpret_cast<uint4*>(smem + (buf) + 1 * A_PL + am * AROW + aq * 16) = L;  \
    } while (0)

    #define CPASYNC_B(buf, ch) do {                                                    \
        int k0c = kbase + (ch) * CHK;                                                  \
        _Pragma("unroll")                                                              \
        for (int i = 0; i < 2; i++) {                                                  \
            int seg = tid + 512 * i;                                                   \
            int plane = seg >> 9, rem = seg & 511, row = rem >> 2, kq = rem & 3;       \
            const __half* src = g_B + (plane * 128 + row) * 2048 + k0c + kq * 8;       \
            CP16(sb + (buf) + A_SZ + plane * B_PL + row * AROW + kq * 16, src);        \
        }                                                                              \
        CP_COMMIT();                                                                   \
    } while (0)

    // ---- prologue ----
    LOAD_A(0);
    STORE_A(0u);
    CPASYNC_B(0u, 0);
    LOAD_A(1);

    #pragma unroll 1
    for (int c = 0; c < NCH; c++) {
        const uint32_t cur = (uint32_t)((c & 1) * BUF);
        const uint32_t nxt = (uint32_t)(((c + 1) & 1) * BUF);

        CP_WAIT0();        // B buffer c landed (own groups)
        __syncthreads();   // publish all copies/stores; close reads of buffer nxt

        if (c + 1 < NCH) {
            STORE_A(nxt);
            CPASYNC_B(nxt, c + 1);
        }
        if (c + 2 < NCH) LOAD_A(c + 2);

        const uint32_t aB = sb + cur;
        const uint32_t bB = sb + cur + A_SZ;

        // ---- software-pipelined fragment schedule (volatile order is honored) ----
        uint32_t Ah0[2][4], Al0[2][4], Bh0[2][4], Bl0[2][4];
        uint32_t Ah1[2][4], Al1[2][4], Bh1[2][4], Bl1[2][4];

        ldsm_A(Ah0, aB, m0, a_lane, 0, 0);
        ldsm_B(Bh0, bB, n0w, b_lane, 0, 0);
        ldsm_A(Al0, aB, m0, a_lane, 0, A_PL);
        ldsm_B(Bl0, bB, n0w, b_lane, 0, B_PL);

        pass(acc, Ah0, Bh0);                    // hh(0)
        pass(acc, Ah0, Bl0);                    // hl(0)   (Ah0, Bl0 die)

        ldsm_A(Ah1, aB, m0, a_lane, 1, 0);      // prefetch s=1 H under lh(0)
        ldsm_B(Bh1, bB, n0w, b_lane, 1, 0);

        pass(acc, Al0, Bh0);                    // lh(0)   (Al0, Bh0 die)

        ldsm_A(Al1, aB, m0, a_lane, 1, A_PL);   // prefetch s=1 L under hh(1)
        ldsm_B(Bl1, bB, n0w, b_lane, 1, B_PL);

        pass(acc, Ah1, Bh1);                    // hh(1)
        pass(acc, Ah1, Bl1);                    // hl(1)
        pass(acc, Al1, Bh1);                    // lh(1)
    }

    // ---- epilogue: write k-split partials ----
    float* gp = g_part + (long)ks * NTOK * 128;
    #pragma unroll
    for (int mf = 0; mf < 2; mf++) {
        int tok = (int)t0 + m0 + mf * 16 + (lane >> 2);
        #pragma unroll
        for (int nf = 0; nf < 4; nf++) {
            int col = n0w + nf * 8 + (lane & 3) * 2;
            *reinterpret_cast<float2*>(&gp[(long)tok * 128 + col]) =
                make_float2(acc[mf][nf][0], acc[mf][nf][1]);
            *reinterpret_cast<float2*>(&gp[(long)(tok + 8) * 128 + col]) =
                make_float2(acc[mf][nf][2], acc[mf][nf][3]);
        }
    }

    // ---- arrival: second CTA of this tile runs the router ----
    __threadfence();
    if (tid == 0) {
        int old = atomicAdd(&g_ctr[tile], 1);
        s_flag = (old == 1);
        if (old == 1) g_ctr[tile] = 0;   // self-reset for graph replay
    }
    __syncthreads();
    if (!s_flag) return;
    __threadfence();   // acquire peer CTA's partials

    #pragma unroll 1
    for (int i = 0; i < 8; i++) {
        long t = t0 + wid * 8 + i;
        const float* P0 = g_part + t * 128;
        const float* P1 = g_part + (NTOK + t) * 128;
        float g0 = P0[lane]       + P1[lane];
        float g1 = P0[lane + 32]  + P1[lane + 32];
        float n0 = P0[64 + lane]  + P1[64 + lane];
        float n1 = P0[96 + lane]  + P1[96 + lane];
        float l0 = g0 + softplus_f(n0) * eps[t * NE + lane];
        float l1 = g1 + softplus_f(n1) * eps[t * NE + lane + 32];

        float v1, v2; int i1, i2;
        if (l0 >= l1) { v1 = l0; i1 = lane;      v2 = l1; i2 = lane + 32; }
        else          { v1 = l1; i1 = lane + 32; v2 = l0; i2 = lane; }
        #pragma unroll
        for (int off = 16; off; off >>= 1) {
            float ov1 = __shfl_xor_sync(0xffffffffu, v1, off);
            int   oi1 = __shfl_xor_sync(0xffffffffu, i1, off);
            float ov2 = __shfl_xor_sync(0xffffffffu, v2, off);
            int   oi2 = __shfl_xor_sync(0xffffffffu, i2, off);
            top2_merge(v1, i1, v2, i2, ov1, oi1, ov2, oi2);
        }

        float e  = expf(v2 - v1);
        float p1 = 1.0f / (1.0f + e);
        float p2 = e * p1;

        float pr0 = (lane == i1) ? p1 : ((lane == i2) ? p2 : 0.0f);
        float pr1 = ((lane + 32) == i1) ? p1 : (((lane + 32) == i2) ? p2 : 0.0f);
        out[P_OFF + t * NE + lane]      = pr0;
        out[P_OFF + t * NE + lane + 32] = pr1;
        if (lane == 0) {
            out[I_OFF + t * 2 + 0] = (float)i1;
            out[I_OFF + t * 2 + 1] = (float)i2;
        }
        out[M_OFF + t * NE + lane]      = (lane == i1) ? 1.0f : 0.0f;
        out[M_OFF + t * NE + lane + 32] = ((lane + 32) == i1) ? 1.0f : 0.0f;
        out[M_OFF + (long)NTOK * NE + t * NE + lane]      = (lane == i2) ? 1.0f : 0.0f;
        out[M_OFF + (long)NTOK * NE + t * NE + lane + 32] = ((lane + 32) == i2) ? 1.0f : 0.0f;
    }
}

extern "C" void kernel_launch(void* const* d_in, const int* in_sizes, int n_in,
                              void* d_out, int out_size)
{
    const float* x   = (const float*)d_in[0];  // [4,2048,2048]
    const float* eps = (const float*)d_in[1];  // [4,2048,64]
    const float* wg  = (const float*)d_in[2];  // [2048,64]
    const float* wn  = (const float*)d_in[3];  // [2048,64]
    float* out = (float*)d_out;

    cudaFuncSetAttribute(gemm_fused, cudaFuncAttributeMaxDynamicSharedMemorySize, SMEMB);
    prep_b<<<128, 256>>>(wg, wn);
    gemm_fused<<<128, 512, SMEMB>>>(x, eps, out);
}

// round 12
// speedup vs baseline: 1.0753x; 1.0753x over previous
#include <cuda_runtime.h>
#include <cuda_fp16.h>
#include <cstdint>
#include <cmath>

// ---------------- problem constants ----------------
#define NTOK 8192      // B*T
#define DDIM 2048
#define NE   64

// output layout (concatenated float32)
#define P_OFF 0
#define I_OFF (NTOK * NE)
#define M_OFF (I_OFF + NTOK * 2)

// ---------------- GEMM tiling ----------------
#define KSPLIT 2
#define KQ     1024           // K per split
#define CHK    32             // k per chunk
#define NCH    32             // chunks (KQ/CHK)
#define AROW   80             // smem row stride bytes (64B data + 16B pad)
#define A_PL   (128 * AROW)   // A plane: 128 tokens (10240)
#define B_PL   (128 * AROW)   // B plane: 128 cols   (10240)
#define A_SZ   (2 * A_PL)     // 20480
#define B_SZ   (2 * B_PL)     // 20480
#define BUF    (A_SZ + B_SZ)  // 40960
#define SMEMB  (2 * BUF)      // 81920, double buffered

// named barrier ids (FULL: producer->consumer, EMPTY: consumer->producer)
#define BFULL0 1
#define BFULL1 2
#define BEMPTY0 3
#define BEMPTY1 4
#define BAR_SYNC(id)   asm volatile("bar.sync %0, 512;"   :: "r"(id) : "memory")
#define BAR_ARRIVE(id) asm volatile("bar.arrive %0, 512;" :: "r"(id) : "memory")

// ---------------- scratch ----------------
__device__ __align__(16) __half g_B[2 * 128 * 2048];   // [plane][col][k] fp16
__device__ float g_part[KSPLIT * NTOK * 128];          // k-split partials (8MB)
__device__ int   g_ctr[64];                            // per-tile counters (self-reset)

// ---------------- helpers ----------------
__device__ __forceinline__ uint32_t smem_u32(const void* p) {
    uint32_t a;
    asm("{ .reg .u64 t; cvta.to.shared.u64 t, %1; cvt.u32.u64 %0, t; }" : "=r"(a) : "l"(p));
    return a;
}
#define CP16(dst, src) \
    asm volatile("cp.async.cg.shared.global [%0], [%1], 16;" :: "r"(dst), "l"(src) : "memory")
#define CP_COMMIT() asm volatile("cp.async.commit_group;" ::: "memory")
#define CP_WAIT0()  asm volatile("cp.async.wait_group 0;" ::: "memory")

__device__ __forceinline__ void ldsm4(uint32_t (&r)[4], uint32_t addr) {
    asm volatile("ldmatrix.sync.aligned.m8n8.x4.shared.b16 {%0,%1,%2,%3}, [%4];"
                 : "=r"(r[0]), "=r"(r[1]), "=r"(r[2]), "=r"(r[3]) : "r"(addr));
}
__device__ __forceinline__ void mma16816(float (&c)[4], const uint32_t (&a)[4],
                                         uint32_t b0, uint32_t b1) {
    asm volatile(
        "mma.sync.aligned.m16n8k16.row.col.f32.f16.f16.f32 "
        "{%0,%1,%2,%3},{%4,%5,%6,%7},{%8,%9},{%0,%1,%2,%3};"
        : "+f"(c[0]), "+f"(c[1]), "+f"(c[2]), "+f"(c[3])
        : "r"(a[0]), "r"(a[1]), "r"(a[2]), "r"(a[3]), "r"(b0), "r"(b1));
}
__device__ __forceinline__ uint32_t h2_bits(__half2 v) {
    return *reinterpret_cast<uint32_t*>(&v);
}
__device__ __forceinline__ void split8h(const float* f, uint4& H, uint4& L) {
    uint32_t hw[4], lw[4];
    #pragma unroll
    for (int i = 0; i < 4; i++) {
        float a = f[2 * i], b = f[2 * i + 1];
        __half2 hp = __floats2half2_rn(a, b);
        float ra = a - __low2float(hp);
        float rb = b - __high2float(hp);
        __half2 lp = __floats2half2_rn(ra, rb);
        hw[i] = h2_bits(hp); lw[i] = h2_bits(lp);
    }
    H = make_uint4(hw[0], hw[1], hw[2], hw[3]);
    L = make_uint4(lw[0], lw[1], lw[2], lw[3]);
}
__device__ __forceinline__ float softplus_f(float v) {
    return (v > 20.0f) ? v : log1pf(expf(v));
}
__device__ __forceinline__ void top2_merge(float& v1, int& i1, float& v2, int& i2,
                                           float ov1, int oi1, float ov2, int oi2) {
    bool ow = (ov1 > v1) || (ov1 == v1 && oi1 < i1);
    float nv1 = ow ? ov1 : v1;  int ni1 = ow ? oi1 : i1;
    float lv  = ow ? v1  : ov1; int li  = ow ? i1  : oi1;
    float wv2 = ow ? ov2 : v2;  int wi2 = ow ? oi2 : i2;
    bool sw = (lv > wv2) || (lv == wv2 && li < wi2);
    v1 = nv1; i1 = ni1;
    v2 = sw ? lv : wv2; i2 = sw ? li : wi2;
}

// ---------------- prep: w -> g_B[2][128 col][2048 k] fp16, smem transpose ----------------
__global__ __launch_bounds__(256) void prep_b(const float* __restrict__ wg,
                                              const float* __restrict__ wn) {
    __shared__ __align__(16) __half sh[2][64][36];
    const int tid = threadIdx.x;
    const int h  = blockIdx.x & 1;
    const int k0 = (blockIdx.x >> 1) * 32;
    const float* w = h ? wn : wg;

    #pragma unroll
    for (int i = 0; i < 8; i++) {
        int fid = i * 256 + tid;
        int kk = fid >> 6;
        int n  = fid & 63;
        float a = w[(k0 + kk) * 64 + n];
        __half hh = __float2half_rn(a);
        __half hl = __float2half_rn(a - __half2float(hh));
        sh[0][n][kk] = hh;
        sh[1][n][kk] = hl;
    }
    __syncthreads();

    #pragma unroll
    for (int i = 0; i < 4; i++) {
        int fid = i * 256 + tid;
        int plane = fid >> 9;
        int rem = fid & 511;
        int row = rem >> 3;
        int kq  = rem & 7;
        uint2 v = *reinterpret_cast<const uint2*>(&sh[plane][row][kq * 4]);
        *reinterpret_cast<uint2*>(&g_B[(plane * 128 + h * 64 + row) * 2048 + k0 + kq * 4]) = v;
    }
}

// ---------------- fused warp-specialized GEMM + router ----------------
__global__ __launch_bounds__(512, 1) void gemm_fused(
    const float* __restrict__ x, const float* __restrict__ eps,
    float* __restrict__ out)
{
    extern __shared__ char smem[];
    __shared__ int s_flag;
    const uint32_t sb = smem_u32(smem);
    const int tid  = threadIdx.x;
    const int wid  = tid >> 5;
    const int lane = tid & 31;
    const int tile = blockIdx.x >> 1;
    const int ks   = blockIdx.x & 1;
    const long t0  = (long)tile * 128;
    const int kbase = ks * KQ;

    float acc[2][8][4];
    #pragma unroll
    for (int a = 0; a < 2; a++)
        #pragma unroll
        for (int b = 0; b < 8; b++)
            #pragma unroll
            for (int c = 0; c < 4; c++) acc[a][b][c] = 0.0f;

    if (wid >= 8) {
        // ======================= PRODUCER =======================
        const int ptid = tid - 256;           // 0..255
        const int am  = ptid >> 1;            // token row
        const int ah  = ptid & 1;             // 16-float half of the 32-k chunk
        float4 sx0, sx1, sx2, sx3;

        #define P_LOAD(ch) do {                                                        \
            const float4* px = reinterpret_cast<const float4*>(                        \
                x + (t0 + am) * DDIM + kbase + (ch) * CHK + ah * 16);                  \
            sx0 = px[0]; sx1 = px[1]; sx2 = px[2]; sx3 = px[3];                        \
        } while (0)

        #define P_STORE(buf) do {                                                      \
            uint4 H, L;                                                                \
            { float f[8] = {sx0.x, sx0.y, sx0.z, sx0.w, sx1.x, sx1.y, sx1.z, sx1.w};   \
              split8h(f, H, L);                                                        \
              *reinterpret_cast<uint4*>(smem + (buf) + 0 * A_PL + am * AROW + ah * 32) = H; \
              *reinterpret_cast<uint4*>(smem + (buf) + 1 * A_PL + am * AROW + ah * 32) = L; } \
            { float f[8] = {sx2.x, sx2.y, sx2.z, sx2.w, sx3.x, sx3.y, sx3.z, sx3.w};   \
              split8h(f, H, L);                                                        \
              *reinterpret_cast<uint4*>(smem + (buf) + 0 * A_PL + am * AROW + ah * 32 + 16) = H; \
              *reinterpret_cast<uint4*>(smem + (buf) + 1 * A_PL + am * AROW + ah * 32 + 16) = L; } \
        } while (0)

        #define P_CPB(buf, ch) do {                                                    \
            int k0c = kbase + (ch) * CHK;                                              \
            _Pragma("unroll")                                                          \
            for (int i = 0; i < 4; i++) {                                              \
                int seg = ptid + 256 * i;                                              \
                int plane = seg >> 9, rem = seg & 511, row = rem >> 2, kq = rem & 3;   \
                const __half* src = g_B + (plane * 128 + row) * 2048 + k0c + kq * 8;   \
                CP16(sb + (buf) + A_SZ + plane * B_PL + row * AROW + kq * 16, src);    \
            }                                                                          \
            CP_COMMIT();                                                               \
        } while (0)

        P_LOAD(0);
        #pragma unroll 1
        for (int c = 0; c < NCH; c++) {
            const uint32_t buf = (uint32_t)((c & 1) * BUF);
            if (c >= 2) BAR_SYNC((c & 1) ? BEMPTY1 : BEMPTY0);
            P_STORE(buf);
            P_CPB(buf, c);
            if (c + 1 < NCH) P_LOAD(c + 1);
            CP_WAIT0();
            BAR_ARRIVE((c & 1) ? BFULL1 : BFULL0);
        }
    } else {
        // ======================= CONSUMER =======================
        const int m0c = (wid & 3) * 32;
        const int n0c = (wid >> 2) * 64;
        const int t4 = lane >> 3, r8 = lane & 7;
        const uint32_t a_lane = (uint32_t)(((t4 & 1) * 8 + r8) * AROW + (t4 >> 1) * 16);
        const uint32_t b_lane = (uint32_t)(((t4 >> 1) * 8 + r8) * AROW + (t4 & 1) * 16);

        // 12 MMAs for one 16-col q-group, all three terms
        #define QMMA(q, BH, BL) do {                                                   \
            mma16816(acc[0][2*(q)  ], Ah[0], BH[0], BH[1]);                            \
            mma16816(acc[0][2*(q)+1], Ah[0], BH[2], BH[3]);                            \
            mma16816(acc[1][2*(q)  ], Ah[1], BH[0], BH[1]);                            \
            mma16816(acc[1][2*(q)+1], Ah[1], BH[2], BH[3]);                            \
            mma16816(acc[0][2*(q)  ], Ah[0], BL[0], BL[1]);                            \
            mma16816(acc[0][2*(q)+1], Ah[0], BL[2], BL[3]);                            \
            mma16816(acc[1][2*(q)  ], Ah[1], BL[0], BL[1]);                            \
            mma16816(acc[1][2*(q)+1], Ah[1], BL[2], BL[3]);                            \
            mma16816(acc[0][2*(q)  ], Al[0], BH[0], BH[1]);                            \
            mma16816(acc[0][2*(q)+1], Al[0], BH[2], BH[3]);                            \
            mma16816(acc[1][2*(q)  ], Al[1], BH[0], BH[1]);                            \
            mma16816(acc[1][2*(q)+1], Al[1], BH[2], BH[3]);                            \
        } while (0)

        #pragma unroll 1
        for (int c = 0; c < NCH; c++) {
            const uint32_t cur = (uint32_t)((c & 1) * BUF);
            BAR_SYNC((c & 1) ? BFULL1 : BFULL0);

            const uint32_t aB = sb + cur;
            const uint32_t bB = sb + cur + A_SZ;
            #pragma unroll
            for (int s = 0; s < 2; s++) {
                uint32_t Ah[2][4], Al[2][4];
                ldsm4(Ah[0], aB + (uint32_t)((m0c)      * AROW) + a_lane + s * 32);
                ldsm4(Ah[1], aB + (uint32_t)((m0c + 16) * AROW) + a_lane + s * 32);
                ldsm4(Al[0], aB + A_PL + (uint32_t)((m0c)      * AROW) + a_lane + s * 32);
                ldsm4(Al[1], aB + A_PL + (uint32_t)((m0c + 16) * AROW) + a_lane + s * 32);
                uint32_t B0h[4], B0l[4], B1h[4], B1l[4];
                ldsm4(B0h, bB + (uint32_t)((n0c)      * AROW) + b_lane + s * 32);
                ldsm4(B0l, bB + B_PL + (uint32_t)((n0c)      * AROW) + b_lane + s * 32);
                ldsm4(B1h, bB + (uint32_t)((n0c + 16) * AROW) + b_lane + s * 32);
                ldsm4(B1l, bB + B_PL + (uint32_t)((n0c + 16) * AROW) + b_lane + s * 32);
                QMMA(0, B0h, B0l);
                ldsm4(B0h, bB + (uint32_t)((n0c + 32) * AROW) + b_lane + s * 32);
                ldsm4(B0l, bB + B_PL + (uint32_t)((n0c + 32) * AROW) + b_lane + s * 32);
                QMMA(1, B1h, B1l);
                ldsm4(B1h, bB + (uint32_t)((n0c + 48) * AROW) + b_lane + s * 32);
                ldsm4(B1l, bB + B_PL + (uint32_t)((n0c + 48) * AROW) + b_lane + s * 32);
                QMMA(2, B0h, B0l);
                QMMA(3, B1h, B1l);
            }
            BAR_ARRIVE((c & 1) ? BEMPTY1 : BEMPTY0);
        }

        // write k-split partials
        float* gp = g_part + (long)ks * NTOK * 128;
        #pragma unroll
        for (int mf = 0; mf < 2; mf++) {
            int tok = (int)t0 + m0c + mf * 16 + (lane >> 2);
            #pragma unroll
            for (int nf = 0; nf < 8; nf++) {
                int col = n0c + nf * 8 + (lane & 3) * 2;
                *reinterpret_cast<float2*>(&gp[(long)tok * 128 + col]) =
                    make_float2(acc[mf][nf][0], acc[mf][nf][1]);
                *reinterpret_cast<float2*>(&gp[(long)(tok + 8) * 128 + col]) =
                    make_float2(acc[mf][nf][2], acc[mf][nf][3]);
            }
        }
    }

    // ---- arrival: second CTA of this tile runs the router (all 16 warps) ----
    __threadfence();
    __syncthreads();
    if (tid == 0) {
        int old = atomicAdd(&g_ctr[tile], 1);
        s_flag = (old == 1);
        if (old == 1) g_ctr[tile] = 0;   // self-reset for graph replay
    }
    __syncthreads();
    if (!s_flag) return;
    __threadfence();   // acquire peer CTA's partials

    #pragma unroll 1
    for (int i = 0; i < 8; i++) {
        long t = t0 + wid * 8 + i;
        const float* P0 = g_part + t * 128;
        const float* P1 = g_part + (NTOK + t) * 128;
        float g0 = P0[lane]       + P1[lane];
        float g1 = P0[lane + 32]  + P1[lane + 32];
        float n0 = P0[64 + lane]  + P1[64 + lane];
        float n1 = P0[96 + lane]  + P1[96 + lane];
        float l0 = g0 + softplus_f(n0) * eps[t * NE + lane];
        float l1 = g1 + softplus_f(n1) * eps[t * NE + lane + 32];

        float v1, v2; int i1, i2;
        if (l0 >= l1) { v1 = l0; i1 = lane;      v2 = l1; i2 = lane + 32; }
        else          { v1 = l1; i1 = lane + 32; v2 = l0; i2 = lane; }
        #pragma unroll
        for (int off = 16; off; off >>= 1) {
            float ov1 = __shfl_xor_sync(0xffffffffu, v1, off);
            int   oi1 = __shfl_xor_sync(0xffffffffu, i1, off);
            float ov2 = __shfl_xor_sync(0xffffffffu, v2, off);
            int   oi2 = __shfl_xor_sync(0xffffffffu, i2, off);
            top2_merge(v1, i1, v2, i2, ov1, oi1, ov2, oi2);
        }

        float e  = expf(v2 - v1);
        float p1 = 1.0f / (1.0f + e);
        float p2 = e * p1;

        float pr0 = (lane == i1) ? p1 : ((lane == i2) ? p2 : 0.0f);
        float pr1 = ((lane + 32) == i1) ? p1 : (((lane + 32) == i2) ? p2 : 0.0f);
        out[P_OFF + t * NE + lane]      = pr0;
        out[P_OFF + t * NE + lane + 32] = pr1;
        if (lane == 0) {
            out[I_OFF + t * 2 + 0] = (float)i1;
            out[I_OFF + t * 2 + 1] = (float)i2;
        }
        out[M_OFF + t * NE + lane]      = (lane == i1) ? 1.0f : 0.0f;
        out[M_OFF + t * NE + lane + 32] = ((lane + 32) == i1) ? 1.0f : 0.0f;
        out[M_OFF + (long)NTOK * NE + t * NE + lane]      = (lane == i2) ? 1.0f : 0.0f;
        out[M_OFF + (long)NTOK * NE + t * NE + lane + 32] = ((lane + 32) == i2) ? 1.0f : 0.0f;
    }
}

extern "C" void kernel_launch(void* const* d_in, const int* in_sizes, int n_in,
                              void* d_out, int out_size)
{
    const float* x   = (const float*)d_in[0];  // [4,2048,2048]
    const float* eps = (const float*)d_in[1];  // [4,2048,64]
    const float* wg  = (const float*)d_in[2];  // [2048,64]
    const float* wn  = (const float*)d_in[3];  // [2048,64]
    float* out = (float*)d_out;

    cudaFuncSetAttribute(gemm_fused, cudaFuncAttributeMaxDynamicSharedMemorySize, SMEMB);
    prep_b<<<128, 256>>>(wg, wn);
    gemm_fused<<<128, 512, SMEMB>>>(x, eps, out);
}